// round 14
// baseline (speedup 1.0000x reference)
#include <cuda_runtime.h>
#include <cuda_bf16.h>
#include <cfloat>
#include <math.h>
#include <cstdint>

#define DDIM 256
#define MAXK 2048
#define MAXN (1 << 17)
#define CAP  32

__device__ float  g_cn[MAXK];
__device__ float  g_zn[MAXN];
__device__ float  g_be[MAXN];        // per-row provable score-error band
__device__ int    g_idx[MAXN];
__device__ int    g_flag_cnt;
__device__ int    g_flagged[MAXN];
__device__ int    g_ccnt[MAXN];
__device__ unsigned long long g_cand[(size_t)MAXN * CAP];
__device__ double g_loss_acc;
__device__ __align__(16) __nv_bfloat16 g_ehi[MAXK * DDIM];

// ---------------- key packing ----------------
__device__ __forceinline__ unsigned long long packkey(float s, int idx) {
    unsigned u = __float_as_uint(s);
    u = (u & 0x80000000u) ? ~u : (u | 0x80000000u);
    return ((unsigned long long)u << 32) | (unsigned)idx;
}
__device__ __forceinline__ float unpackval(unsigned long long k) {
    unsigned u = (unsigned)(k >> 32);
    u = (u & 0x80000000u) ? (u ^ 0x80000000u) : ~u;
    return __uint_as_float(u);
}
__device__ __forceinline__ float band_thr(float m, float be) {
    const float am = fabsf(m);
    const float qq = (am > 0.f) ? exp2f((float)(ilogbf(am) - 22)) : 1e-30f;
    return m + 2.0f * qq + be;
}

// ---------------- PTX helpers (baseline ISA) ----------------
__device__ __forceinline__ uint32_t smem_u32(const void* p) {
    uint32_t a;
    asm("{ .reg .u64 t; cvta.to.shared.u64 t, %1; cvt.u32.u64 %0, t; }"
        : "=r"(a) : "l"(p));
    return a;
}
__device__ __forceinline__ void ldsm_x4(uint32_t* r, uint32_t addr) {
    asm volatile("ldmatrix.sync.aligned.m8n8.x4.shared.b16 {%0,%1,%2,%3}, [%4];"
                 : "=r"(r[0]), "=r"(r[1]), "=r"(r[2]), "=r"(r[3]) : "r"(addr));
}
__device__ __forceinline__ void ldsm_x2(uint32_t* r, uint32_t addr) {
    asm volatile("ldmatrix.sync.aligned.m8n8.x2.shared.b16 {%0,%1}, [%2];"
                 : "=r"(r[0]), "=r"(r[1]) : "r"(addr));
}
__device__ __forceinline__ void mma16816(float* c, const uint32_t* a,
                                         const uint32_t* b) {
    asm volatile(
        "mma.sync.aligned.m16n8k16.row.col.f32.bf16.bf16.f32 "
        "{%0,%1,%2,%3}, {%4,%5,%6,%7}, {%8,%9}, {%0,%1,%2,%3};"
        : "+f"(c[0]), "+f"(c[1]), "+f"(c[2]), "+f"(c[3])
        : "r"(a[0]), "r"(a[1]), "r"(a[2]), "r"(a[3]), "r"(b[0]), "r"(b[1]));
}
__device__ __forceinline__ void cp16(uint32_t saddr, const void* gaddr) {
    asm volatile("cp.async.ca.shared.global [%0], [%1], 16;"
                 :: "r"(saddr), "l"(gaddr) : "memory");
}
__device__ __forceinline__ void cp_commit() {
    asm volatile("cp.async.commit_group;" ::: "memory");
}
__device__ __forceinline__ void cp_wait1() {
    asm volatile("cp.async.wait_group 1;" ::: "memory");
}
__device__ __forceinline__ void cp_wait0() {
    asm volatile("cp.async.wait_group 0;" ::: "memory");
}
__device__ __forceinline__ int chunk_sw(int c, int r) {
    return (c & ~7) | ((c ^ r) & 7);
}

// SMEM layout (bytes) — full-chunk double-buffered e tiles, 1 CTA/SM
#define SM_ZHI  0            // 128 rows x 512B = 64KB
#define SM_E    65536        // 2 x 64KB e_hi stage buffers
#define SM_KEYS 196608       // 128 x u64
#define SM_CCNT 197632       // 128 x int
#define SM_BE   198144       // 128 x float
#define SM_TOTAL 198656

// ---------------------------------------------------------------------------
// K1: fp64 norms -> fp32; per-row error band; reset accumulators.
// ---------------------------------------------------------------------------
__global__ void k_norms(const float* __restrict__ z,
                        const float* __restrict__ emb, int N) {
    const int b = blockIdx.x;
    const int t = threadIdx.x;
    const float* src = (b < N) ? (z + (size_t)b * DDIM)
                               : (emb + (size_t)(b - N) * DDIM);
    const float x = src[t];
    double v = (double)x * (double)x;
    float  a = fabsf(x);
    float  l = fabsf(x - __bfloat162float(__float2bfloat16(x)));
    __shared__ double s[8];
    __shared__ float  sa[8], sl[8];
    #pragma unroll
    for (int o = 16; o; o >>= 1) {
        v += __shfl_down_sync(0xFFFFFFFFu, v, o);
        a += __shfl_down_sync(0xFFFFFFFFu, a, o);
        l += __shfl_down_sync(0xFFFFFFFFu, l, o);
    }
    if ((t & 31) == 0) { s[t >> 5] = v; sa[t >> 5] = a; sl[t >> 5] = l; }
    __syncthreads();
    if (t == 0) {
        double sum = 0.0;
        float asum = 0.f, lsum2 = 0.f;
        #pragma unroll
        for (int i = 0; i < 8; i++) { sum += s[i]; asum += sa[i]; lsum2 += sl[i]; }
        if (b < N) {
            g_zn[b] = (float)sum;
            g_be[b] = 2.0f * (1e-3f * lsum2 + 2e-6f * asum) + 3e-4f;
        } else g_cn[b - N] = (float)sum;
        if (b == 0) { g_loss_acc = 0.0; g_flag_cnt = 0; }
    }
}

__global__ void k_econv(const float* __restrict__ emb) {
    const int i = blockIdx.x * 256 + threadIdx.x;
    g_ehi[i] = __float2bfloat16(emb[i]);
}

// ---------------------------------------------------------------------------
// K2: 1-term bf16 GEMM z_hi.e_hi via mma.sync + fused running-min + candidate
//     superset collection. 8 full-chunk double-buffered stages, 24 barriers.
// ---------------------------------------------------------------------------
__global__ void __launch_bounds__(256, 1)
k_gemm(const float4* __restrict__ z, int K) {
    extern __shared__ char smem[];
    const uint32_t sb = smem_u32(smem);
    unsigned long long* keys = (unsigned long long*)(smem + SM_KEYS);
    int*   ccnt = (int*)(smem + SM_CCNT);
    float* sbe  = (float*)(smem + SM_BE);
    const int tid = threadIdx.x;
    const int lane = tid & 31;
    const int wid = tid >> 5;
    const int row0 = blockIdx.x * 128;
    const int warp_m = wid >> 2;
    const int warp_n = wid & 3;

    if (tid < 128) {
        keys[tid] = ~0ull;
        ccnt[tid] = 0;
        sbe[tid]  = g_be[row0 + tid];
    }

    // ---- z_hi tile: fp32 -> bf16, swizzled 16B chunks (32/row) ----
    for (int i = tid; i < 128 * 32; i += 256) {
        const int r = i >> 5;
        const int c = i & 31;
        const float4 v0 = z[(size_t)(row0 + r) * 64 + c * 2];
        const float4 v1 = z[(size_t)(row0 + r) * 64 + c * 2 + 1];
        const float xs[8] = {v0.x, v0.y, v0.z, v0.w, v1.x, v1.y, v1.z, v1.w};
        uint32_t hw[4];
        #pragma unroll
        for (int q = 0; q < 4; q++) {
            hw[q] = (uint32_t)__bfloat16_as_ushort(__float2bfloat16(xs[2 * q]))
                  | ((uint32_t)__bfloat16_as_ushort(
                         __float2bfloat16(xs[2 * q + 1])) << 16);
        }
        const int off = r * 512 + chunk_sw(c, r) * 16;
        *(uint4*)(smem + SM_ZHI + off) = make_uint4(hw[0], hw[1], hw[2], hw[3]);
    }

    float znA[4], znB[4];
    #pragma unroll
    for (int mt = 0; mt < 4; mt++) {
        znA[mt] = g_zn[row0 + warp_m * 64 + mt * 16 + (lane >> 2)];
        znB[mt] = g_zn[row0 + warp_m * 64 + mt * 16 + (lane >> 2) + 8];
    }

    const int nchunk = K / 128;

    // full-chunk prefetch: 128 codes x 256 dims bf16 (64KB), buffer = kc&1
    auto prefetch = [&](int kc) {
        const uint4* shi = (const uint4*)(g_ehi + (size_t)kc * 128 * DDIM);
        const uint32_t dst = sb + SM_E + (uint32_t)(kc & 1) * 65536;
        #pragma unroll
        for (int i = tid; i < 128 * 32; i += 256) {
            const int r = i >> 5;
            const int c = i & 31;
            const uint32_t off = (uint32_t)(r * 512 + chunk_sw(c, r) * 16);
            cp16(dst + off, &shi[r * 32 + c]);
        }
    };

    prefetch(0);
    cp_commit();

    for (int kc = 0; kc < nchunk; kc++) {
        const int k0 = kc * 128;

        // prefetch next chunk into the other buffer (safe: compute of kc-1
        // finished at the epilogue barrier of the previous iteration)
        if (kc + 1 < nchunk) { prefetch(kc + 1); cp_commit(); cp_wait1(); }
        else                 { cp_wait0(); }
        __syncthreads();

        const uint32_t ebase = sb + SM_E + (uint32_t)(kc & 1) * 65536;

        float acc[4][4][4];
        #pragma unroll
        for (int mt = 0; mt < 4; mt++)
            #pragma unroll
            for (int nt = 0; nt < 4; nt++)
                #pragma unroll
                for (int q = 0; q < 4; q++) acc[mt][nt][q] = 0.f;

        #pragma unroll 4
        for (int ks = 0; ks < 16; ks++) {
            uint32_t ahi[4][4], bhi[4][2];
            #pragma unroll
            for (int mt = 0; mt < 4; mt++) {
                const int r = warp_m * 64 + mt * 16 + (lane & 15);
                const int c = ks * 2 + (lane >> 4);
                const uint32_t off =
                    (uint32_t)(r * 512 + chunk_sw(c, r) * 16);
                ldsm_x4(ahi[mt], sb + SM_ZHI + off);
            }
            #pragma unroll
            for (int nt = 0; nt < 4; nt++) {
                const int n = warp_n * 32 + nt * 8 + (lane & 7);
                const int c = ks * 2 + ((lane >> 3) & 1);
                const uint32_t off =
                    (uint32_t)(n * 512 + chunk_sw(c, n) * 16);
                ldsm_x2(bhi[nt], ebase + off);
            }
            #pragma unroll
            for (int mt = 0; mt < 4; mt++)
                #pragma unroll
                for (int nt = 0; nt < 4; nt++)
                    mma16816(acc[mt][nt], ahi[mt], bhi[nt]);
        }

        // ---- epilogue A: scores (into acc) + running row-min ----
        #pragma unroll
        for (int mt = 0; mt < 4; mt++) {
            const int lrA = warp_m * 64 + mt * 16 + (lane >> 2);
            const int lrB = lrA + 8;
            unsigned long long mkA = ~0ull, mkB = ~0ull;
            #pragma unroll
            for (int nt = 0; nt < 4; nt++) {
                const int col = k0 + warp_n * 32 + nt * 8 + (lane & 3) * 2;
                const float cn0 = g_cn[col], cn1 = g_cn[col + 1];
                const float sAx = (znA[mt] + cn0) - 2.0f * acc[mt][nt][0];
                const float sAy = (znA[mt] + cn1) - 2.0f * acc[mt][nt][1];
                const float sBx = (znB[mt] + cn0) - 2.0f * acc[mt][nt][2];
                const float sBy = (znB[mt] + cn1) - 2.0f * acc[mt][nt][3];
                acc[mt][nt][0] = sAx; acc[mt][nt][1] = sAy;
                acc[mt][nt][2] = sBx; acc[mt][nt][3] = sBy;
                mkA = min(mkA, min(packkey(sAx, col), packkey(sAy, col + 1)));
                mkB = min(mkB, min(packkey(sBx, col), packkey(sBy, col + 1)));
            }
            mkA = min(mkA, __shfl_xor_sync(0xFFFFFFFFu, mkA, 1));
            mkA = min(mkA, __shfl_xor_sync(0xFFFFFFFFu, mkA, 2));
            mkB = min(mkB, __shfl_xor_sync(0xFFFFFFFFu, mkB, 1));
            mkB = min(mkB, __shfl_xor_sync(0xFFFFFFFFu, mkB, 2));
            if ((lane & 3) == 0) {
                atomicMin(&keys[lrA], mkA);
                atomicMin(&keys[lrB], mkB);
            }
        }
        __syncthreads();

        // ---- epilogue B: collect superset candidates -> global ----
        #pragma unroll
        for (int mt = 0; mt < 4; mt++) {
            const int lrA = warp_m * 64 + mt * 16 + (lane >> 2);
            const int lrB = lrA + 8;
            const float thrA = band_thr(unpackval(keys[lrA]), sbe[lrA]);
            const float thrB = band_thr(unpackval(keys[lrB]), sbe[lrB]);
            #pragma unroll
            for (int nt = 0; nt < 4; nt++) {
                const int col = k0 + warp_n * 32 + nt * 8 + (lane & 3) * 2;
                if (acc[mt][nt][0] <= thrA) {
                    const int p = atomicAdd(&ccnt[lrA], 1);
                    if (p < CAP)
                        g_cand[(size_t)(row0 + lrA) * CAP + p] =
                            packkey(acc[mt][nt][0], col);
                }
                if (acc[mt][nt][1] <= thrA) {
                    const int p = atomicAdd(&ccnt[lrA], 1);
                    if (p < CAP)
                        g_cand[(size_t)(row0 + lrA) * CAP + p] =
                            packkey(acc[mt][nt][1], col + 1);
                }
                if (acc[mt][nt][2] <= thrB) {
                    const int p = atomicAdd(&ccnt[lrB], 1);
                    if (p < CAP)
                        g_cand[(size_t)(row0 + lrB) * CAP + p] =
                            packkey(acc[mt][nt][2], col);
                }
                if (acc[mt][nt][3] <= thrB) {
                    const int p = atomicAdd(&ccnt[lrB], 1);
                    if (p < CAP)
                        g_cand[(size_t)(row0 + lrB) * CAP + p] =
                            packkey(acc[mt][nt][3], col + 1);
                }
            }
        }
        __syncthreads();
    }

    if (tid < 128) g_ccnt[row0 + tid] = ccnt[tid];
}

// ---------------------------------------------------------------------------
// K3: resolve winners only. Single-candidate fast path; fp64 rescore else.
// ---------------------------------------------------------------------------
__global__ void __launch_bounds__(256)
k_resolve(const float* __restrict__ z, const float* __restrict__ emb,
          float* __restrict__ out_idx_f) {
    const int warp = threadIdx.x >> 5;
    const int lane = threadIdx.x & 31;
    const int row  = blockIdx.x * 8 + warp;

    const int cnt = g_ccnt[row];
    if (cnt > CAP) {
        if (lane == 0) {
            const int p = atomicAdd(&g_flag_cnt, 1);
            g_flagged[p] = row;
        }
        return;
    }

    unsigned long long ck = (lane < cnt) ? g_cand[(size_t)row * CAP + lane]
                                         : ~0ull;
    unsigned long long mn = ck;
    #pragma unroll
    for (int o = 16; o; o >>= 1)
        mn = min(mn, __shfl_xor_sync(0xFFFFFFFFu, mn, o));
    const float thr = band_thr(unpackval(mn), g_be[row]);
    const bool valid = (lane < cnt) && (unpackval(ck) <= thr);
    unsigned mask = __ballot_sync(0xFFFFFFFFu, valid);

    int win;
    if (__popc(mask) == 1) {
        win = (int)(unsigned)(mn & 0xFFFFFFFFull);
    } else {
        float zreg[8];
        const float* zr = z + (size_t)row * DDIM;
        #pragma unroll
        for (int t = 0; t < 8; t++) zreg[t] = zr[lane + 32 * t];
        const float zn = g_zn[row];

        unsigned long long best = ~0ull;
        while (mask) {
            const int l1 = __ffs(mask) - 1; mask &= mask - 1;
            int l2 = l1;
            if (mask) { l2 = __ffs(mask) - 1; mask &= mask - 1; }
            const int i1 = (int)(unsigned)(__shfl_sync(0xFFFFFFFFu, ck, l1)
                                           & 0xFFFFFFFFull);
            const int i2 = (int)(unsigned)(__shfl_sync(0xFFFFFFFFu, ck, l2)
                                           & 0xFFFFFFFFull);
            const float* e1 = emb + (size_t)i1 * DDIM;
            const float* e2 = emb + (size_t)i2 * DDIM;
            double d1 = 0.0, d2 = 0.0;
            #pragma unroll
            for (int t = 0; t < 8; t++) {
                const double zd = (double)zreg[t];
                d1 += zd * (double)__ldg(e1 + lane + 32 * t);
                d2 += zd * (double)__ldg(e2 + lane + 32 * t);
            }
            #pragma unroll
            for (int o = 16; o; o >>= 1) {
                d1 += __shfl_down_sync(0xFFFFFFFFu, d1, o);
                d2 += __shfl_down_sync(0xFFFFFFFFu, d2, o);
            }
            if (lane == 0) {
                const float s1 = (zn + g_cn[i1]) - 2.0f * (float)d1;
                best = min(best, packkey(s1, i1));
                if (i2 != i1) {
                    const float s2 = (zn + g_cn[i2]) - 2.0f * (float)d2;
                    best = min(best, packkey(s2, i2));
                }
            }
        }
        win = (int)(unsigned)(__shfl_sync(0xFFFFFFFFu, best, 0)
                              & 0xFFFFFFFFull);
    }
    if (lane == 0) {
        g_idx[row] = win;
        out_idx_f[row] = (float)win;
    }
}

// ---------------------------------------------------------------------------
// K4: full-K fp64 fallback (rare): index only.
// ---------------------------------------------------------------------------
__global__ void k_fallback(const float* __restrict__ z,
                           const float* __restrict__ emb,
                           float* __restrict__ out_idx_f, int K) {
    __shared__ float zrow[DDIM];
    __shared__ unsigned long long best;
    const int cnt = g_flag_cnt;
    for (int f = blockIdx.x; f < cnt; f += gridDim.x) {
        const int row = g_flagged[f];
        if (threadIdx.x == 0) best = ~0ull;
        for (int t = threadIdx.x; t < DDIM; t += blockDim.x)
            zrow[t] = z[(size_t)row * DDIM + t];
        __syncthreads();
        const float zn = g_zn[row];
        unsigned long long lb = ~0ull;
        for (int k = threadIdx.x; k < K; k += blockDim.x) {
            double dot = 0.0;
            const float* ek = emb + (size_t)k * DDIM;
            #pragma unroll 8
            for (int d = 0; d < DDIM; d++)
                dot += (double)zrow[d] * (double)ek[d];
            const float s = (zn + g_cn[k]) - 2.0f * (float)dot;
            lb = min(lb, packkey(s, k));
        }
        atomicMin(&best, lb);
        __syncthreads();
        if (threadIdx.x == 0) {
            const int win = (int)(unsigned)(best & 0xFFFFFFFFull);
            g_idx[row] = win;
            out_idx_f[row] = (float)win;
        }
        __syncthreads();
    }
}

// ---------------------------------------------------------------------------
// K5: streaming gather + straight-through + loss (block-reduced).
// ---------------------------------------------------------------------------
__global__ void k_gather(const float4* __restrict__ z,
                         const float4* __restrict__ emb,
                         float4* __restrict__ outq, int total4) {
    double lsum = 0.0;
    const int stride = gridDim.x * blockDim.x;
    for (int e = blockIdx.x * blockDim.x + threadIdx.x; e < total4; e += stride) {
        const int row = e >> 6;
        const int t   = e & 63;
        const int idx = g_idx[row];
        const float4 ev = emb[(size_t)idx * 64 + t];
        const float4 zv = z[e];
        const float dx = ev.x - zv.x, dy = ev.y - zv.y;
        const float dz = ev.z - zv.z, dw = ev.w - zv.w;
        float4 o;
        o.x = zv.x + dx; o.y = zv.y + dy; o.z = zv.z + dz; o.w = zv.w + dw;
        outq[e] = o;
        lsum += (double)(dx * dx) + (double)(dy * dy)
              + (double)(dz * dz) + (double)(dw * dw);
    }
    __shared__ double s[8];
    #pragma unroll
    for (int o = 16; o; o >>= 1) lsum += __shfl_down_sync(0xFFFFFFFFu, lsum, o);
    if ((threadIdx.x & 31) == 0) s[threadIdx.x >> 5] = lsum;
    __syncthreads();
    if (threadIdx.x == 0) {
        double b = 0.0;
        #pragma unroll
        for (int i = 0; i < 8; i++) b += s[i];
        atomicAdd(&g_loss_acc, b);
    }
}

__global__ void k_final(float* __restrict__ out_loss, double inv_cnt) {
    *out_loss = (float)(0.25 * g_loss_acc * inv_cnt);
}

// ---------------------------------------------------------------------------
extern "C" void kernel_launch(void* const* d_in, const int* in_sizes, int n_in,
                              void* d_out, int out_size) {
    const float* z   = (const float*)d_in[0];
    const float* emb = (const float*)d_in[1];
    const int N = in_sizes[0] / DDIM;
    const int K = in_sizes[1] / DDIM;

    float* out      = (float*)d_out;
    float* out_q    = out;
    float* out_idx  = out + (size_t)N * DDIM;
    float* out_loss = out_idx + N;

    k_norms<<<N + K, 256>>>(z, emb, N);
    k_econv<<<K, 256>>>(emb);

    cudaFuncSetAttribute(k_gemm, cudaFuncAttributeMaxDynamicSharedMemorySize,
                         SM_TOTAL);
    k_gemm<<<N / 128, 256, SM_TOTAL>>>((const float4*)z, K);

    k_resolve<<<N / 8, 256>>>(z, emb, out_idx);
    k_fallback<<<1024, 256>>>(z, emb, out_idx, K);

    k_gather<<<1024, 256>>>((const float4*)z, (const float4*)emb,
                            (float4*)out_q, N * (DDIM / 4));

    k_final<<<1, 1>>>(out_loss, 1.0 / ((double)N * (double)DDIM));
}

// round 15
// speedup vs baseline: 1.4535x; 1.4535x over previous
#include <cuda_runtime.h>
#include <cuda_bf16.h>
#include <cfloat>
#include <math.h>
#include <cstdint>

#define DDIM 256
#define MAXK 2048
#define MAXN (1 << 17)
#define CAP  32

__device__ float  g_cn[MAXK];
__device__ float  g_zn[MAXN];
__device__ float  g_be[MAXN];        // per-row provable score-error band
__device__ int    g_idx[MAXN];
__device__ int    g_flag_cnt;        // rows with candidate overflow -> full-K
__device__ int    g_flagged[MAXN];
__device__ int    g_amb_cnt;         // rows with >1 in-band candidate
__device__ int    g_amb[MAXN];
__device__ int    g_ccnt[MAXN];
__device__ unsigned long long g_cand[(size_t)MAXN * CAP];
__device__ double g_loss_acc;
__device__ __align__(16) __nv_bfloat16 g_ehi[MAXK * DDIM];

// ---------------- key packing ----------------
__device__ __forceinline__ unsigned long long packkey(float s, int idx) {
    unsigned u = __float_as_uint(s);
    u = (u & 0x80000000u) ? ~u : (u | 0x80000000u);
    return ((unsigned long long)u << 32) | (unsigned)idx;
}
__device__ __forceinline__ float unpackval(unsigned long long k) {
    unsigned u = (unsigned)(k >> 32);
    u = (u & 0x80000000u) ? (u ^ 0x80000000u) : ~u;
    return __uint_as_float(u);
}
// branch-free band: >= 4 ulp(m) for all m of interest, monotone in m
__device__ __forceinline__ float band_thr(float m, float be) {
    return m + fabsf(m) * 2.4e-7f + be;
}

// ---------------- PTX helpers (baseline ISA) ----------------
__device__ __forceinline__ uint32_t smem_u32(const void* p) {
    uint32_t a;
    asm("{ .reg .u64 t; cvta.to.shared.u64 t, %1; cvt.u32.u64 %0, t; }"
        : "=r"(a) : "l"(p));
    return a;
}
__device__ __forceinline__ void ldsm_x4(uint32_t* r, uint32_t addr) {
    asm volatile("ldmatrix.sync.aligned.m8n8.x4.shared.b16 {%0,%1,%2,%3}, [%4];"
                 : "=r"(r[0]), "=r"(r[1]), "=r"(r[2]), "=r"(r[3]) : "r"(addr));
}
__device__ __forceinline__ void ldsm_x2(uint32_t* r, uint32_t addr) {
    asm volatile("ldmatrix.sync.aligned.m8n8.x2.shared.b16 {%0,%1}, [%2];"
                 : "=r"(r[0]), "=r"(r[1]) : "r"(addr));
}
__device__ __forceinline__ void mma16816(float* c, const uint32_t* a,
                                         const uint32_t* b) {
    asm volatile(
        "mma.sync.aligned.m16n8k16.row.col.f32.bf16.bf16.f32 "
        "{%0,%1,%2,%3}, {%4,%5,%6,%7}, {%8,%9}, {%0,%1,%2,%3};"
        : "+f"(c[0]), "+f"(c[1]), "+f"(c[2]), "+f"(c[3])
        : "r"(a[0]), "r"(a[1]), "r"(a[2]), "r"(a[3]), "r"(b[0]), "r"(b[1]));
}
__device__ __forceinline__ void cp16(uint32_t saddr, const void* gaddr) {
    asm volatile("cp.async.ca.shared.global [%0], [%1], 16;"
                 :: "r"(saddr), "l"(gaddr) : "memory");
}
__device__ __forceinline__ void cp_commit() {
    asm volatile("cp.async.commit_group;" ::: "memory");
}
__device__ __forceinline__ void cp_wait1() {
    asm volatile("cp.async.wait_group 1;" ::: "memory");
}
__device__ __forceinline__ void cp_wait0() {
    asm volatile("cp.async.wait_group 0;" ::: "memory");
}
__device__ __forceinline__ int chunk_sw(int c, int r) {
    return (c & ~7) | ((c ^ r) & 7);
}

// SMEM layout (bytes) — R13 config (quarter-D dbuf, ~102KB, 2 CTAs/SM)
#define SM_ZHI  0            // 128 rows x 512B = 64KB
#define SM_E    65536        // 2 x 16KB e_hi stage buffers
#define SM_KEYS 98304        // 128 x u64
#define SM_CCNT 99328        // 128 x int
#define SM_BE   99840        // 128 x float
#define SM_CN   100352       // K floats (<= 4KB for K=1024)
#define SM_TOTAL 104448

// ---------------------------------------------------------------------------
// K1: fp64 norms -> fp32; per-row error band; reset accumulators.
//     Warp per row: blocks of 8 rows.
// ---------------------------------------------------------------------------
__global__ void k_norms(const float* __restrict__ z,
                        const float* __restrict__ emb, int N) {
    const int warp = threadIdx.x >> 5;
    const int lane = threadIdx.x & 31;
    const int b = blockIdx.x * 8 + warp;
    const float* src = (b < N) ? (z + (size_t)b * DDIM)
                               : (emb + (size_t)(b - N) * DDIM);
    double v = 0.0;
    float  a = 0.f, l = 0.f;
    #pragma unroll
    for (int t = 0; t < 8; t++) {
        const float x = src[lane + 32 * t];
        v += (double)x * (double)x;
        a += fabsf(x);
        l += fabsf(x - __bfloat162float(__float2bfloat16(x)));
    }
    #pragma unroll
    for (int o = 16; o; o >>= 1) {
        v += __shfl_down_sync(0xFFFFFFFFu, v, o);
        a += __shfl_down_sync(0xFFFFFFFFu, a, o);
        l += __shfl_down_sync(0xFFFFFFFFu, l, o);
    }
    if (lane == 0) {
        if (b < N) {
            g_zn[b] = (float)v;
            g_be[b] = 2.0f * (1e-3f * l + 2e-6f * a) + 3e-4f;
        } else g_cn[b - N] = (float)v;
    }
    if (blockIdx.x == 0 && threadIdx.x == 0) {
        g_loss_acc = 0.0; g_flag_cnt = 0; g_amb_cnt = 0;
    }
}

__global__ void k_econv(const float* __restrict__ emb) {
    const int i = blockIdx.x * 256 + threadIdx.x;
    g_ehi[i] = __float2bfloat16(emb[i]);
}

// ---------------------------------------------------------------------------
// K2: 1-term bf16 GEMM z_hi.e_hi via mma.sync + fused running-min + candidate
//     superset collection. R13 staging; c-norms cached in SMEM.
// ---------------------------------------------------------------------------
__global__ void __launch_bounds__(256, 2)
k_gemm(const float4* __restrict__ z, int K) {
    extern __shared__ char smem[];
    const uint32_t sb = smem_u32(smem);
    unsigned long long* keys = (unsigned long long*)(smem + SM_KEYS);
    int*   ccnt = (int*)(smem + SM_CCNT);
    float* sbe  = (float*)(smem + SM_BE);
    float* cn_s = (float*)(smem + SM_CN);
    const int tid = threadIdx.x;
    const int lane = tid & 31;
    const int wid = tid >> 5;
    const int row0 = blockIdx.x * 128;
    const int warp_m = wid >> 2;
    const int warp_n = wid & 3;

    if (tid < 128) {
        keys[tid] = ~0ull;
        ccnt[tid] = 0;
        sbe[tid]  = g_be[row0 + tid];
    }
    for (int i = tid; i < K; i += 256) cn_s[i] = g_cn[i];

    // ---- z_hi tile: fp32 -> bf16, swizzled 16B chunks (32/row) ----
    for (int i = tid; i < 128 * 32; i += 256) {
        const int r = i >> 5;
        const int c = i & 31;
        const float4 v0 = z[(size_t)(row0 + r) * 64 + c * 2];
        const float4 v1 = z[(size_t)(row0 + r) * 64 + c * 2 + 1];
        const float xs[8] = {v0.x, v0.y, v0.z, v0.w, v1.x, v1.y, v1.z, v1.w};
        uint32_t hw[4];
        #pragma unroll
        for (int q = 0; q < 4; q++) {
            hw[q] = (uint32_t)__bfloat16_as_ushort(__float2bfloat16(xs[2 * q]))
                  | ((uint32_t)__bfloat16_as_ushort(
                         __float2bfloat16(xs[2 * q + 1])) << 16);
        }
        const int off = r * 512 + chunk_sw(c, r) * 16;
        *(uint4*)(smem + SM_ZHI + off) = make_uint4(hw[0], hw[1], hw[2], hw[3]);
    }

    float znA[4], znB[4];
    #pragma unroll
    for (int mt = 0; mt < 4; mt++) {
        znA[mt] = g_zn[row0 + warp_m * 64 + mt * 16 + (lane >> 2)];
        znB[mt] = g_zn[row0 + warp_m * 64 + mt * 16 + (lane >> 2) + 8];
    }

    const int nchunk = K / 128;
    const int nstage = nchunk * 4;

    auto prefetch = [&](int s) {
        const int kc = s >> 2, qd = s & 3;
        const uint4* shi = (const uint4*)(g_ehi + (size_t)kc * 128 * DDIM);
        const uint32_t dst = sb + SM_E + (uint32_t)(s & 1) * 16384;
        #pragma unroll
        for (int i = tid; i < 128 * 8; i += 256) {
            const int r = i >> 3;
            const int c = i & 7;
            const uint32_t off = (uint32_t)(r * 128 + ((c ^ r) & 7) * 16);
            cp16(dst + off, &shi[r * 32 + qd * 8 + c]);
        }
    };

    prefetch(0);
    cp_commit();

    for (int kc = 0; kc < nchunk; kc++) {
        const int k0 = kc * 128;

        float acc[4][4][4];
        #pragma unroll
        for (int mt = 0; mt < 4; mt++)
            #pragma unroll
            for (int nt = 0; nt < 4; nt++)
                #pragma unroll
                for (int q = 0; q < 4; q++) acc[mt][nt][q] = 0.f;

        #pragma unroll 1
        for (int qd = 0; qd < 4; qd++) {
            const int s = kc * 4 + qd;
            if (s + 1 < nstage) { prefetch(s + 1); cp_commit(); cp_wait1(); }
            else                { cp_wait0(); }
            __syncthreads();

            const uint32_t ebase = sb + SM_E + (uint32_t)(s & 1) * 16384;
            #pragma unroll
            for (int ks = 0; ks < 4; ks++) {
                uint32_t ahi[4][4], bhi[4][2];
                #pragma unroll
                for (int mt = 0; mt < 4; mt++) {
                    const int r = warp_m * 64 + mt * 16 + (lane & 15);
                    const int c = qd * 8 + ks * 2 + (lane >> 4);
                    const uint32_t off =
                        (uint32_t)(r * 512 + chunk_sw(c, r) * 16);
                    ldsm_x4(ahi[mt], sb + SM_ZHI + off);
                }
                #pragma unroll
                for (int nt = 0; nt < 4; nt++) {
                    const int n = warp_n * 32 + nt * 8 + (lane & 7);
                    const int c = ks * 2 + ((lane >> 3) & 1);
                    const uint32_t off =
                        (uint32_t)(n * 128 + ((c ^ n) & 7) * 16);
                    ldsm_x2(bhi[nt], ebase + off);
                }
                #pragma unroll
                for (int mt = 0; mt < 4; mt++)
                    #pragma unroll
                    for (int nt = 0; nt < 4; nt++)
                        mma16816(acc[mt][nt], ahi[mt], bhi[nt]);
            }
            __syncthreads();
        }

        // ---- epilogue A: scores (into acc) + running row-min ----
        #pragma unroll
        for (int mt = 0; mt < 4; mt++) {
            const int lrA = warp_m * 64 + mt * 16 + (lane >> 2);
            const int lrB = lrA + 8;
            unsigned long long mkA = ~0ull, mkB = ~0ull;
            #pragma unroll
            for (int nt = 0; nt < 4; nt++) {
                const int col = k0 + warp_n * 32 + nt * 8 + (lane & 3) * 2;
                const float cn0 = cn_s[col], cn1 = cn_s[col + 1];
                const float sAx = (znA[mt] + cn0) - 2.0f * acc[mt][nt][0];
                const float sAy = (znA[mt] + cn1) - 2.0f * acc[mt][nt][1];
                const float sBx = (znB[mt] + cn0) - 2.0f * acc[mt][nt][2];
                const float sBy = (znB[mt] + cn1) - 2.0f * acc[mt][nt][3];
                acc[mt][nt][0] = sAx; acc[mt][nt][1] = sAy;
                acc[mt][nt][2] = sBx; acc[mt][nt][3] = sBy;
                mkA = min(mkA, min(packkey(sAx, col), packkey(sAy, col + 1)));
                mkB = min(mkB, min(packkey(sBx, col), packkey(sBy, col + 1)));
            }
            mkA = min(mkA, __shfl_xor_sync(0xFFFFFFFFu, mkA, 1));
            mkA = min(mkA, __shfl_xor_sync(0xFFFFFFFFu, mkA, 2));
            mkB = min(mkB, __shfl_xor_sync(0xFFFFFFFFu, mkB, 1));
            mkB = min(mkB, __shfl_xor_sync(0xFFFFFFFFu, mkB, 2));
            if ((lane & 3) == 0) {
                atomicMin(&keys[lrA], mkA);
                atomicMin(&keys[lrB], mkB);
            }
        }
        __syncthreads();

        // ---- epilogue B: collect superset candidates -> global ----
        #pragma unroll
        for (int mt = 0; mt < 4; mt++) {
            const int lrA = warp_m * 64 + mt * 16 + (lane >> 2);
            const int lrB = lrA + 8;
            const float thrA = band_thr(unpackval(keys[lrA]), sbe[lrA]);
            const float thrB = band_thr(unpackval(keys[lrB]), sbe[lrB]);
            #pragma unroll
            for (int nt = 0; nt < 4; nt++) {
                const int col = k0 + warp_n * 32 + nt * 8 + (lane & 3) * 2;
                if (acc[mt][nt][0] <= thrA) {
                    const int p = atomicAdd(&ccnt[lrA], 1);
                    if (p < CAP)
                        g_cand[(size_t)(row0 + lrA) * CAP + p] =
                            packkey(acc[mt][nt][0], col);
                }
                if (acc[mt][nt][1] <= thrA) {
                    const int p = atomicAdd(&ccnt[lrA], 1);
                    if (p < CAP)
                        g_cand[(size_t)(row0 + lrA) * CAP + p] =
                            packkey(acc[mt][nt][1], col + 1);
                }
                if (acc[mt][nt][2] <= thrB) {
                    const int p = atomicAdd(&ccnt[lrB], 1);
                    if (p < CAP)
                        g_cand[(size_t)(row0 + lrB) * CAP + p] =
                            packkey(acc[mt][nt][2], col);
                }
                if (acc[mt][nt][3] <= thrB) {
                    const int p = atomicAdd(&ccnt[lrB], 1);
                    if (p < CAP)
                        g_cand[(size_t)(row0 + lrB) * CAP + p] =
                            packkey(acc[mt][nt][3], col + 1);
                }
            }
        }
        __syncthreads();
    }

    if (tid < 128) g_ccnt[row0 + tid] = ccnt[tid];
}

// ---------------------------------------------------------------------------
// K3: streaming thread-per-row resolve. Unique-in-band -> provable argmin.
//     Ambiguous rows pushed to g_amb; overflow rows to g_flagged.
// ---------------------------------------------------------------------------
__global__ void __launch_bounds__(256)
k_resolve(float* __restrict__ out_idx_f) {
    const int row = blockIdx.x * 256 + threadIdx.x;
    const int cnt = g_ccnt[row];
    if (cnt > CAP) {
        const int p = atomicAdd(&g_flag_cnt, 1);
        g_flagged[p] = row;
        return;
    }
    const unsigned long long* cr = g_cand + (size_t)row * CAP;
    unsigned long long mn = ~0ull;
    for (int i = 0; i < cnt; i++) mn = min(mn, __ldg(cr + i));
    const float thr = band_thr(unpackval(mn), g_be[row]);
    int nval = 0;
    for (int i = 0; i < cnt; i++)
        nval += (unpackval(__ldg(cr + i)) <= thr) ? 1 : 0;
    if (nval <= 1) {
        const int win = (int)(unsigned)(mn & 0xFFFFFFFFull);
        g_idx[row] = win;
        out_idx_f[row] = (float)win;
    } else {
        const int p = atomicAdd(&g_amb_cnt, 1);
        g_amb[p] = row;
    }
}

// ---------------------------------------------------------------------------
// K3b: warp-per-row exact fp64 rescore for ambiguous rows.
// ---------------------------------------------------------------------------
__global__ void __launch_bounds__(256)
k_resolve2(const float* __restrict__ z, const float* __restrict__ emb,
           float* __restrict__ out_idx_f) {
    const int lane = threadIdx.x & 31;
    const int gw = blockIdx.x * 8 + (threadIdx.x >> 5);
    const int nwarps = gridDim.x * 8;
    const int acnt = g_amb_cnt;

    for (int i = gw; i < acnt; i += nwarps) {
        const int row = g_amb[i];
        const int cnt = g_ccnt[row];
        unsigned long long ck = (lane < cnt)
            ? g_cand[(size_t)row * CAP + lane] : ~0ull;
        unsigned long long mn = ck;
        #pragma unroll
        for (int o = 16; o; o >>= 1)
            mn = min(mn, __shfl_xor_sync(0xFFFFFFFFu, mn, o));
        const float thr = band_thr(unpackval(mn), g_be[row]);
        const bool valid = (lane < cnt) && (unpackval(ck) <= thr);
        unsigned mask = __ballot_sync(0xFFFFFFFFu, valid);

        float zreg[8];
        const float* zr = z + (size_t)row * DDIM;
        #pragma unroll
        for (int t = 0; t < 8; t++) zreg[t] = zr[lane + 32 * t];
        const float zn = g_zn[row];

        unsigned long long best = ~0ull;
        while (mask) {
            const int l1 = __ffs(mask) - 1; mask &= mask - 1;
            int l2 = l1;
            if (mask) { l2 = __ffs(mask) - 1; mask &= mask - 1; }
            const int i1 = (int)(unsigned)(__shfl_sync(0xFFFFFFFFu, ck, l1)
                                           & 0xFFFFFFFFull);
            const int i2 = (int)(unsigned)(__shfl_sync(0xFFFFFFFFu, ck, l2)
                                           & 0xFFFFFFFFull);
            const float* e1 = emb + (size_t)i1 * DDIM;
            const float* e2 = emb + (size_t)i2 * DDIM;
            double d1 = 0.0, d2 = 0.0;
            #pragma unroll
            for (int t = 0; t < 8; t++) {
                const double zd = (double)zreg[t];
                d1 += zd * (double)__ldg(e1 + lane + 32 * t);
                d2 += zd * (double)__ldg(e2 + lane + 32 * t);
            }
            #pragma unroll
            for (int o = 16; o; o >>= 1) {
                d1 += __shfl_down_sync(0xFFFFFFFFu, d1, o);
                d2 += __shfl_down_sync(0xFFFFFFFFu, d2, o);
            }
            if (lane == 0) {
                const float s1 = (zn + g_cn[i1]) - 2.0f * (float)d1;
                best = min(best, packkey(s1, i1));
                if (i2 != i1) {
                    const float s2 = (zn + g_cn[i2]) - 2.0f * (float)d2;
                    best = min(best, packkey(s2, i2));
                }
            }
        }
        if (lane == 0) {
            const int win = (int)(unsigned)(best & 0xFFFFFFFFull);
            g_idx[row] = win;
            out_idx_f[row] = (float)win;
        }
    }
}

// ---------------------------------------------------------------------------
// K4: full-K fp64 fallback (rare): index only.
// ---------------------------------------------------------------------------
__global__ void k_fallback(const float* __restrict__ z,
                           const float* __restrict__ emb,
                           float* __restrict__ out_idx_f, int K) {
    __shared__ float zrow[DDIM];
    __shared__ unsigned long long best;
    const int cnt = g_flag_cnt;
    for (int f = blockIdx.x; f < cnt; f += gridDim.x) {
        const int row = g_flagged[f];
        if (threadIdx.x == 0) best = ~0ull;
        for (int t = threadIdx.x; t < DDIM; t += blockDim.x)
            zrow[t] = z[(size_t)row * DDIM + t];
        __syncthreads();
        const float zn = g_zn[row];
        unsigned long long lb = ~0ull;
        for (int k = threadIdx.x; k < K; k += blockDim.x) {
            double dot = 0.0;
            const float* ek = emb + (size_t)k * DDIM;
            #pragma unroll 8
            for (int d = 0; d < DDIM; d++)
                dot += (double)zrow[d] * (double)ek[d];
            const float s = (zn + g_cn[k]) - 2.0f * (float)dot;
            lb = min(lb, packkey(s, k));
        }
        atomicMin(&best, lb);
        __syncthreads();
        if (threadIdx.x == 0) {
            const int win = (int)(unsigned)(best & 0xFFFFFFFFull);
            g_idx[row] = win;
            out_idx_f[row] = (float)win;
        }
        __syncthreads();
    }
}

// ---------------------------------------------------------------------------
// K5: streaming gather + straight-through + loss (block-reduced).
// ---------------------------------------------------------------------------
__global__ void k_gather(const float4* __restrict__ z,
                         const float4* __restrict__ emb,
                         float4* __restrict__ outq, int total4) {
    double lsum = 0.0;
    const int stride = gridDim.x * blockDim.x;
    for (int e = blockIdx.x * blockDim.x + threadIdx.x; e < total4; e += stride) {
        const int row = e >> 6;
        const int t   = e & 63;
        const int idx = g_idx[row];
        const float4 ev = emb[(size_t)idx * 64 + t];
        const float4 zv = z[e];
        const float dx = ev.x - zv.x, dy = ev.y - zv.y;
        const float dz = ev.z - zv.z, dw = ev.w - zv.w;
        float4 o;
        o.x = zv.x + dx; o.y = zv.y + dy; o.z = zv.z + dz; o.w = zv.w + dw;
        outq[e] = o;
        lsum += (double)(dx * dx) + (double)(dy * dy)
              + (double)(dz * dz) + (double)(dw * dw);
    }
    __shared__ double s[8];
    #pragma unroll
    for (int o = 16; o; o >>= 1) lsum += __shfl_down_sync(0xFFFFFFFFu, lsum, o);
    if ((threadIdx.x & 31) == 0) s[threadIdx.x >> 5] = lsum;
    __syncthreads();
    if (threadIdx.x == 0) {
        double b = 0.0;
        #pragma unroll
        for (int i = 0; i < 8; i++) b += s[i];
        atomicAdd(&g_loss_acc, b);
    }
}

__global__ void k_final(float* __restrict__ out_loss, double inv_cnt) {
    *out_loss = (float)(0.25 * g_loss_acc * inv_cnt);
}

// ---------------------------------------------------------------------------
extern "C" void kernel_launch(void* const* d_in, const int* in_sizes, int n_in,
                              void* d_out, int out_size) {
    const float* z   = (const float*)d_in[0];
    const float* emb = (const float*)d_in[1];
    const int N = in_sizes[0] / DDIM;
    const int K = in_sizes[1] / DDIM;

    float* out      = (float*)d_out;
    float* out_q    = out;
    float* out_idx  = out + (size_t)N * DDIM;
    float* out_loss = out_idx + N;

    k_norms<<<(N + K) / 8, 256>>>(z, emb, N);
    k_econv<<<K, 256>>>(emb);

    cudaFuncSetAttribute(k_gemm, cudaFuncAttributeMaxDynamicSharedMemorySize,
                         SM_TOTAL);
    k_gemm<<<N / 128, 256, SM_TOTAL>>>((const float4*)z, K);

    k_resolve<<<N / 256, 256>>>(out_idx);
    k_resolve2<<<1024, 256>>>(z, emb, out_idx);
    k_fallback<<<1024, 256>>>(z, emb, out_idx, K);

    k_gather<<<1024, 256>>>((const float4*)z, (const float4*)emb,
                            (float4*)out_q, N * (DDIM / 4));

    k_final<<<1, 1>>>(out_loss, 1.0 / ((double)N * (double)DDIM));
}

// round 16
// speedup vs baseline: 1.4573x; 1.0026x over previous
#include <cuda_runtime.h>
#include <cuda_bf16.h>
#include <cfloat>
#include <math.h>
#include <cstdint>

#define DDIM 256
#define MAXK 2048
#define MAXN (1 << 17)
#define CAP  32

__device__ float  g_cn[MAXK];
__device__ float  g_zn[MAXN];
__device__ float  g_be[MAXN];        // per-row provable score-error band
__device__ int    g_idx[MAXN];
__device__ int    g_flag_cnt;        // rows with candidate overflow -> full-K
__device__ int    g_flagged[MAXN];
__device__ int    g_amb_cnt;         // rows with >1 in-band candidate
__device__ int    g_amb[MAXN];
__device__ int    g_ccnt[MAXN];
__device__ unsigned long long g_cand[(size_t)MAXN * CAP];
__device__ double g_loss_acc;
__device__ __align__(16) __nv_bfloat16 g_ehi[MAXK * DDIM];

// ---------------- key packing ----------------
__device__ __forceinline__ unsigned long long packkey(float s, int idx) {
    unsigned u = __float_as_uint(s);
    u = (u & 0x80000000u) ? ~u : (u | 0x80000000u);
    return ((unsigned long long)u << 32) | (unsigned)idx;
}
__device__ __forceinline__ float unpackval(unsigned long long k) {
    unsigned u = (unsigned)(k >> 32);
    u = (u & 0x80000000u) ? (u ^ 0x80000000u) : ~u;
    return __uint_as_float(u);
}
// branch-free band: >= 4 ulp(m) for all m of interest, monotone in m
__device__ __forceinline__ float band_thr(float m, float be) {
    return m + fabsf(m) * 2.4e-7f + be;
}

// ---------------- PTX helpers (baseline ISA) ----------------
__device__ __forceinline__ uint32_t smem_u32(const void* p) {
    uint32_t a;
    asm("{ .reg .u64 t; cvta.to.shared.u64 t, %1; cvt.u32.u64 %0, t; }"
        : "=r"(a) : "l"(p));
    return a;
}
__device__ __forceinline__ void ldsm_x4(uint32_t* r, uint32_t addr) {
    asm volatile("ldmatrix.sync.aligned.m8n8.x4.shared.b16 {%0,%1,%2,%3}, [%4];"
                 : "=r"(r[0]), "=r"(r[1]), "=r"(r[2]), "=r"(r[3]) : "r"(addr));
}
__device__ __forceinline__ void ldsm_x2(uint32_t* r, uint32_t addr) {
    asm volatile("ldmatrix.sync.aligned.m8n8.x2.shared.b16 {%0,%1}, [%2];"
                 : "=r"(r[0]), "=r"(r[1]) : "r"(addr));
}
__device__ __forceinline__ void mma16816(float* c, const uint32_t* a,
                                         const uint32_t* b) {
    asm volatile(
        "mma.sync.aligned.m16n8k16.row.col.f32.bf16.bf16.f32 "
        "{%0,%1,%2,%3}, {%4,%5,%6,%7}, {%8,%9}, {%0,%1,%2,%3};"
        : "+f"(c[0]), "+f"(c[1]), "+f"(c[2]), "+f"(c[3])
        : "r"(a[0]), "r"(a[1]), "r"(a[2]), "r"(a[3]), "r"(b[0]), "r"(b[1]));
}
__device__ __forceinline__ void cp16(uint32_t saddr, const void* gaddr) {
    asm volatile("cp.async.ca.shared.global [%0], [%1], 16;"
                 :: "r"(saddr), "l"(gaddr) : "memory");
}
__device__ __forceinline__ void cp_commit() {
    asm volatile("cp.async.commit_group;" ::: "memory");
}
__device__ __forceinline__ void cp_wait1() {
    asm volatile("cp.async.wait_group 1;" ::: "memory");
}
__device__ __forceinline__ void cp_wait0() {
    asm volatile("cp.async.wait_group 0;" ::: "memory");
}
__device__ __forceinline__ int chunk_sw(int c, int r) {
    return (c & ~7) | ((c ^ r) & 7);
}

// SMEM layout (bytes) — R13 config (quarter-D dbuf, ~102KB, 2 CTAs/SM)
#define SM_ZHI  0            // 128 rows x 512B = 64KB
#define SM_E    65536        // 2 x 16KB e_hi stage buffers
#define SM_KEYS 98304        // 128 x u64
#define SM_CCNT 99328        // 128 x int
#define SM_BE   99840        // 128 x float
#define SM_CN   100352       // K floats (<= 4KB for K=1024)
#define SM_TOTAL 104448

// ---------------------------------------------------------------------------
// K1: fp64 norms -> fp32; per-row error band; reset accumulators.
//     Warp per row: blocks of 8 rows.
// ---------------------------------------------------------------------------
__global__ void k_norms(const float* __restrict__ z,
                        const float* __restrict__ emb, int N) {
    const int warp = threadIdx.x >> 5;
    const int lane = threadIdx.x & 31;
    const int b = blockIdx.x * 8 + warp;
    const float* src = (b < N) ? (z + (size_t)b * DDIM)
                               : (emb + (size_t)(b - N) * DDIM);
    double v = 0.0;
    float  a = 0.f, l = 0.f;
    #pragma unroll
    for (int t = 0; t < 8; t++) {
        const float x = src[lane + 32 * t];
        v += (double)x * (double)x;
        a += fabsf(x);
        l += fabsf(x - __bfloat162float(__float2bfloat16(x)));
    }
    #pragma unroll
    for (int o = 16; o; o >>= 1) {
        v += __shfl_down_sync(0xFFFFFFFFu, v, o);
        a += __shfl_down_sync(0xFFFFFFFFu, a, o);
        l += __shfl_down_sync(0xFFFFFFFFu, l, o);
    }
    if (lane == 0) {
        if (b < N) {
            g_zn[b] = (float)v;
            g_be[b] = 2.0f * (1e-3f * l + 2e-6f * a) + 3e-4f;
        } else g_cn[b - N] = (float)v;
    }
    if (blockIdx.x == 0 && threadIdx.x == 0) {
        g_loss_acc = 0.0; g_flag_cnt = 0; g_amb_cnt = 0;
    }
}

__global__ void k_econv(const float* __restrict__ emb) {
    const int i = blockIdx.x * 256 + threadIdx.x;
    g_ehi[i] = __float2bfloat16(emb[i]);
}

// ---------------------------------------------------------------------------
// K2: 1-term bf16 GEMM z_hi.e_hi via mma.sync + fused running-min + candidate
//     superset collection. R13 staging; c-norms cached in SMEM.
// ---------------------------------------------------------------------------
__global__ void __launch_bounds__(256, 2)
k_gemm(const float4* __restrict__ z, int K) {
    extern __shared__ char smem[];
    const uint32_t sb = smem_u32(smem);
    unsigned long long* keys = (unsigned long long*)(smem + SM_KEYS);
    int*   ccnt = (int*)(smem + SM_CCNT);
    float* sbe  = (float*)(smem + SM_BE);
    float* cn_s = (float*)(smem + SM_CN);
    const int tid = threadIdx.x;
    const int lane = tid & 31;
    const int wid = tid >> 5;
    const int row0 = blockIdx.x * 128;
    const int warp_m = wid >> 2;
    const int warp_n = wid & 3;

    if (tid < 128) {
        keys[tid] = ~0ull;
        ccnt[tid] = 0;
        sbe[tid]  = g_be[row0 + tid];
    }
    for (int i = tid; i < K; i += 256) cn_s[i] = g_cn[i];

    // ---- z_hi tile: fp32 -> bf16, swizzled 16B chunks (32/row) ----
    for (int i = tid; i < 128 * 32; i += 256) {
        const int r = i >> 5;
        const int c = i & 31;
        const float4 v0 = z[(size_t)(row0 + r) * 64 + c * 2];
        const float4 v1 = z[(size_t)(row0 + r) * 64 + c * 2 + 1];
        const float xs[8] = {v0.x, v0.y, v0.z, v0.w, v1.x, v1.y, v1.z, v1.w};
        uint32_t hw[4];
        #pragma unroll
        for (int q = 0; q < 4; q++) {
            hw[q] = (uint32_t)__bfloat16_as_ushort(__float2bfloat16(xs[2 * q]))
                  | ((uint32_t)__bfloat16_as_ushort(
                         __float2bfloat16(xs[2 * q + 1])) << 16);
        }
        const int off = r * 512 + chunk_sw(c, r) * 16;
        *(uint4*)(smem + SM_ZHI + off) = make_uint4(hw[0], hw[1], hw[2], hw[3]);
    }

    float znA[4], znB[4];
    #pragma unroll
    for (int mt = 0; mt < 4; mt++) {
        znA[mt] = g_zn[row0 + warp_m * 64 + mt * 16 + (lane >> 2)];
        znB[mt] = g_zn[row0 + warp_m * 64 + mt * 16 + (lane >> 2) + 8];
    }

    const int nchunk = K / 128;
    const int nstage = nchunk * 4;

    auto prefetch = [&](int s) {
        const int kc = s >> 2, qd = s & 3;
        const uint4* shi = (const uint4*)(g_ehi + (size_t)kc * 128 * DDIM);
        const uint32_t dst = sb + SM_E + (uint32_t)(s & 1) * 16384;
        #pragma unroll
        for (int i = tid; i < 128 * 8; i += 256) {
            const int r = i >> 3;
            const int c = i & 7;
            const uint32_t off = (uint32_t)(r * 128 + ((c ^ r) & 7) * 16);
            cp16(dst + off, &shi[r * 32 + qd * 8 + c]);
        }
    };

    prefetch(0);
    cp_commit();

    for (int kc = 0; kc < nchunk; kc++) {
        const int k0 = kc * 128;

        float acc[4][4][4];
        #pragma unroll
        for (int mt = 0; mt < 4; mt++)
            #pragma unroll
            for (int nt = 0; nt < 4; nt++)
                #pragma unroll
                for (int q = 0; q < 4; q++) acc[mt][nt][q] = 0.f;

        #pragma unroll 1
        for (int qd = 0; qd < 4; qd++) {
            const int s = kc * 4 + qd;
            if (s + 1 < nstage) { prefetch(s + 1); cp_commit(); cp_wait1(); }
            else                { cp_wait0(); }
            __syncthreads();

            const uint32_t ebase = sb + SM_E + (uint32_t)(s & 1) * 16384;
            #pragma unroll
            for (int ks = 0; ks < 4; ks++) {
                uint32_t ahi[4][4], bhi[4][2];
                #pragma unroll
                for (int mt = 0; mt < 4; mt++) {
                    const int r = warp_m * 64 + mt * 16 + (lane & 15);
                    const int c = qd * 8 + ks * 2 + (lane >> 4);
                    const uint32_t off =
                        (uint32_t)(r * 512 + chunk_sw(c, r) * 16);
                    ldsm_x4(ahi[mt], sb + SM_ZHI + off);
                }
                #pragma unroll
                for (int nt = 0; nt < 4; nt++) {
                    const int n = warp_n * 32 + nt * 8 + (lane & 7);
                    const int c = ks * 2 + ((lane >> 3) & 1);
                    const uint32_t off =
                        (uint32_t)(n * 128 + ((c ^ n) & 7) * 16);
                    ldsm_x2(bhi[nt], ebase + off);
                }
                #pragma unroll
                for (int mt = 0; mt < 4; mt++)
                    #pragma unroll
                    for (int nt = 0; nt < 4; nt++)
                        mma16816(acc[mt][nt], ahi[mt], bhi[nt]);
            }
            __syncthreads();
        }

        // ---- epilogue A: scores (into acc) + running row-min ----
        #pragma unroll
        for (int mt = 0; mt < 4; mt++) {
            const int lrA = warp_m * 64 + mt * 16 + (lane >> 2);
            const int lrB = lrA + 8;
            unsigned long long mkA = ~0ull, mkB = ~0ull;
            #pragma unroll
            for (int nt = 0; nt < 4; nt++) {
                const int col = k0 + warp_n * 32 + nt * 8 + (lane & 3) * 2;
                const float cn0 = cn_s[col], cn1 = cn_s[col + 1];
                const float sAx = (znA[mt] + cn0) - 2.0f * acc[mt][nt][0];
                const float sAy = (znA[mt] + cn1) - 2.0f * acc[mt][nt][1];
                const float sBx = (znB[mt] + cn0) - 2.0f * acc[mt][nt][2];
                const float sBy = (znB[mt] + cn1) - 2.0f * acc[mt][nt][3];
                acc[mt][nt][0] = sAx; acc[mt][nt][1] = sAy;
                acc[mt][nt][2] = sBx; acc[mt][nt][3] = sBy;
                mkA = min(mkA, min(packkey(sAx, col), packkey(sAy, col + 1)));
                mkB = min(mkB, min(packkey(sBx, col), packkey(sBy, col + 1)));
            }
            mkA = min(mkA, __shfl_xor_sync(0xFFFFFFFFu, mkA, 1));
            mkA = min(mkA, __shfl_xor_sync(0xFFFFFFFFu, mkA, 2));
            mkB = min(mkB, __shfl_xor_sync(0xFFFFFFFFu, mkB, 1));
            mkB = min(mkB, __shfl_xor_sync(0xFFFFFFFFu, mkB, 2));
            if ((lane & 3) == 0) {
                atomicMin(&keys[lrA], mkA);
                atomicMin(&keys[lrB], mkB);
            }
        }
        __syncthreads();

        // ---- epilogue B: collect superset candidates -> global ----
        #pragma unroll
        for (int mt = 0; mt < 4; mt++) {
            const int lrA = warp_m * 64 + mt * 16 + (lane >> 2);
            const int lrB = lrA + 8;
            const float thrA = band_thr(unpackval(keys[lrA]), sbe[lrA]);
            const float thrB = band_thr(unpackval(keys[lrB]), sbe[lrB]);
            #pragma unroll
            for (int nt = 0; nt < 4; nt++) {
                const int col = k0 + warp_n * 32 + nt * 8 + (lane & 3) * 2;
                if (acc[mt][nt][0] <= thrA) {
                    const int p = atomicAdd(&ccnt[lrA], 1);
                    if (p < CAP)
                        g_cand[(size_t)(row0 + lrA) * CAP + p] =
                            packkey(acc[mt][nt][0], col);
                }
                if (acc[mt][nt][1] <= thrA) {
                    const int p = atomicAdd(&ccnt[lrA], 1);
                    if (p < CAP)
                        g_cand[(size_t)(row0 + lrA) * CAP + p] =
                            packkey(acc[mt][nt][1], col + 1);
                }
                if (acc[mt][nt][2] <= thrB) {
                    const int p = atomicAdd(&ccnt[lrB], 1);
                    if (p < CAP)
                        g_cand[(size_t)(row0 + lrB) * CAP + p] =
                            packkey(acc[mt][nt][2], col);
                }
                if (acc[mt][nt][3] <= thrB) {
                    const int p = atomicAdd(&ccnt[lrB], 1);
                    if (p < CAP)
                        g_cand[(size_t)(row0 + lrB) * CAP + p] =
                            packkey(acc[mt][nt][3], col + 1);
                }
            }
        }
        __syncthreads();
    }

    if (tid < 128) g_ccnt[row0 + tid] = ccnt[tid];
}

// ---------------------------------------------------------------------------
// K3: streaming thread-per-row resolve. Unique-in-band -> provable argmin.
//     Ambiguous rows pushed to g_amb; overflow rows to g_flagged.
// ---------------------------------------------------------------------------
__global__ void __launch_bounds__(256)
k_resolve(float* __restrict__ out_idx_f) {
    const int row = blockIdx.x * 256 + threadIdx.x;
    const int cnt = g_ccnt[row];
    if (cnt > CAP) {
        const int p = atomicAdd(&g_flag_cnt, 1);
        g_flagged[p] = row;
        return;
    }
    const unsigned long long* cr = g_cand + (size_t)row * CAP;
    unsigned long long mn = ~0ull;
    for (int i = 0; i < cnt; i++) mn = min(mn, __ldg(cr + i));
    const float thr = band_thr(unpackval(mn), g_be[row]);
    int nval = 0;
    for (int i = 0; i < cnt; i++)
        nval += (unpackval(__ldg(cr + i)) <= thr) ? 1 : 0;
    if (nval <= 1) {
        const int win = (int)(unsigned)(mn & 0xFFFFFFFFull);
        g_idx[row] = win;
        out_idx_f[row] = (float)win;
    } else {
        const int p = atomicAdd(&g_amb_cnt, 1);
        g_amb[p] = row;
    }
}

// ---------------------------------------------------------------------------
// K3b: warp-per-row exact fp64 rescore for ambiguous rows.
// ---------------------------------------------------------------------------
__global__ void __launch_bounds__(256)
k_resolve2(const float* __restrict__ z, const float* __restrict__ emb,
           float* __restrict__ out_idx_f) {
    const int lane = threadIdx.x & 31;
    const int gw = blockIdx.x * 8 + (threadIdx.x >> 5);
    const int nwarps = gridDim.x * 8;
    const int acnt = g_amb_cnt;

    for (int i = gw; i < acnt; i += nwarps) {
        const int row = g_amb[i];
        const int cnt = g_ccnt[row];
        unsigned long long ck = (lane < cnt)
            ? g_cand[(size_t)row * CAP + lane] : ~0ull;
        unsigned long long mn = ck;
        #pragma unroll
        for (int o = 16; o; o >>= 1)
            mn = min(mn, __shfl_xor_sync(0xFFFFFFFFu, mn, o));
        const float thr = band_thr(unpackval(mn), g_be[row]);
        const bool valid = (lane < cnt) && (unpackval(ck) <= thr);
        unsigned mask = __ballot_sync(0xFFFFFFFFu, valid);

        float zreg[8];
        const float* zr = z + (size_t)row * DDIM;
        #pragma unroll
        for (int t = 0; t < 8; t++) zreg[t] = zr[lane + 32 * t];
        const float zn = g_zn[row];

        unsigned long long best = ~0ull;
        while (mask) {
            const int l1 = __ffs(mask) - 1; mask &= mask - 1;
            int l2 = l1;
            if (mask) { l2 = __ffs(mask) - 1; mask &= mask - 1; }
            const int i1 = (int)(unsigned)(__shfl_sync(0xFFFFFFFFu, ck, l1)
                                           & 0xFFFFFFFFull);
            const int i2 = (int)(unsigned)(__shfl_sync(0xFFFFFFFFu, ck, l2)
                                           & 0xFFFFFFFFull);
            const float* e1 = emb + (size_t)i1 * DDIM;
            const float* e2 = emb + (size_t)i2 * DDIM;
            double d1 = 0.0, d2 = 0.0;
            #pragma unroll
            for (int t = 0; t < 8; t++) {
                const double zd = (double)zreg[t];
                d1 += zd * (double)__ldg(e1 + lane + 32 * t);
                d2 += zd * (double)__ldg(e2 + lane + 32 * t);
            }
            #pragma unroll
            for (int o = 16; o; o >>= 1) {
                d1 += __shfl_down_sync(0xFFFFFFFFu, d1, o);
                d2 += __shfl_down_sync(0xFFFFFFFFu, d2, o);
            }
            if (lane == 0) {
                const float s1 = (zn + g_cn[i1]) - 2.0f * (float)d1;
                best = min(best, packkey(s1, i1));
                if (i2 != i1) {
                    const float s2 = (zn + g_cn[i2]) - 2.0f * (float)d2;
                    best = min(best, packkey(s2, i2));
                }
            }
        }
        if (lane == 0) {
            const int win = (int)(unsigned)(best & 0xFFFFFFFFull);
            g_idx[row] = win;
            out_idx_f[row] = (float)win;
        }
    }
}

// ---------------------------------------------------------------------------
// K4: full-K fp64 fallback (rare): index only.
// ---------------------------------------------------------------------------
__global__ void k_fallback(const float* __restrict__ z,
                           const float* __restrict__ emb,
                           float* __restrict__ out_idx_f, int K) {
    __shared__ float zrow[DDIM];
    __shared__ unsigned long long best;
    const int cnt = g_flag_cnt;
    for (int f = blockIdx.x; f < cnt; f += gridDim.x) {
        const int row = g_flagged[f];
        if (threadIdx.x == 0) best = ~0ull;
        for (int t = threadIdx.x; t < DDIM; t += blockDim.x)
            zrow[t] = z[(size_t)row * DDIM + t];
        __syncthreads();
        const float zn = g_zn[row];
        unsigned long long lb = ~0ull;
        for (int k = threadIdx.x; k < K; k += blockDim.x) {
            double dot = 0.0;
            const float* ek = emb + (size_t)k * DDIM;
            #pragma unroll 8
            for (int d = 0; d < DDIM; d++)
                dot += (double)zrow[d] * (double)ek[d];
            const float s = (zn + g_cn[k]) - 2.0f * (float)dot;
            lb = min(lb, packkey(s, k));
        }
        atomicMin(&best, lb);
        __syncthreads();
        if (threadIdx.x == 0) {
            const int win = (int)(unsigned)(best & 0xFFFFFFFFull);
            g_idx[row] = win;
            out_idx_f[row] = (float)win;
        }
        __syncthreads();
    }
}

// ---------------------------------------------------------------------------
// K5: streaming gather + straight-through + loss (block-reduced).
// ---------------------------------------------------------------------------
__global__ void k_gather(const float4* __restrict__ z,
                         const float4* __restrict__ emb,
                         float4* __restrict__ outq, int total4) {
    double lsum = 0.0;
    const int stride = gridDim.x * blockDim.x;
    for (int e = blockIdx.x * blockDim.x + threadIdx.x; e < total4; e += stride) {
        const int row = e >> 6;
        const int t   = e & 63;
        const int idx = g_idx[row];
        const float4 ev = emb[(size_t)idx * 64 + t];
        const float4 zv = z[e];
        const float dx = ev.x - zv.x, dy = ev.y - zv.y;
        const float dz = ev.z - zv.z, dw = ev.w - zv.w;
        float4 o;
        o.x = zv.x + dx; o.y = zv.y + dy; o.z = zv.z + dz; o.w = zv.w + dw;
        outq[e] = o;
        lsum += (double)(dx * dx) + (double)(dy * dy)
              + (double)(dz * dz) + (double)(dw * dw);
    }
    __shared__ double s[8];
    #pragma unroll
    for (int o = 16; o; o >>= 1) lsum += __shfl_down_sync(0xFFFFFFFFu, lsum, o);
    if ((threadIdx.x & 31) == 0) s[threadIdx.x >> 5] = lsum;
    __syncthreads();
    if (threadIdx.x == 0) {
        double b = 0.0;
        #pragma unroll
        for (int i = 0; i < 8; i++) b += s[i];
        atomicAdd(&g_loss_acc, b);
    }
}

__global__ void k_final(float* __restrict__ out_loss, double inv_cnt) {
    *out_loss = (float)(0.25 * g_loss_acc * inv_cnt);
}

// ---------------------------------------------------------------------------
extern "C" void kernel_launch(void* const* d_in, const int* in_sizes, int n_in,
                              void* d_out, int out_size) {
    const float* z   = (const float*)d_in[0];
    const float* emb = (const float*)d_in[1];
    const int N = in_sizes[0] / DDIM;
    const int K = in_sizes[1] / DDIM;

    float* out      = (float*)d_out;
    float* out_q    = out;
    float* out_idx  = out + (size_t)N * DDIM;
    float* out_loss = out_idx + N;

    k_norms<<<(N + K) / 8, 256>>>(z, emb, N);
    k_econv<<<K, 256>>>(emb);

    cudaFuncSetAttribute(k_gemm, cudaFuncAttributeMaxDynamicSharedMemorySize,
                         SM_TOTAL);
    k_gemm<<<N / 128, 256, SM_TOTAL>>>((const float4*)z, K);

    k_resolve<<<N / 256, 256>>>(out_idx);
    k_resolve2<<<1024, 256>>>(z, emb, out_idx);
    k_fallback<<<1024, 256>>>(z, emb, out_idx, K);

    k_gather<<<1024, 256>>>((const float4*)z, (const float4*)emb,
                            (float4*)out_q, N * (DDIM / 4));

    k_final<<<1, 1>>>(out_loss, 1.0 / ((double)N * (double)DDIM));
}